// round 2
// baseline (speedup 1.0000x reference)
#include <cuda_runtime.h>
#include <math.h>

#define NN 128
#define MM (NN*NN)
#define KTOP 2
#define TMAXS 512
#define STEPF 0.01f
#define EPSV 1e-5f
#define BSZ 512

// ---------------- device scratch (static, no allocations) ----------------
__device__ float g_S [5*MM];   // scaled skew matrices
__device__ float g_P0[5*MM];   // expm ping
__device__ float g_P1[5*MM];   // expm pong
__device__ float g_MA[MM];     // I + STEP*A
__device__ float g_MB[MM];     // STEP*B
__device__ float g_MC[MM];     // C
__device__ float g_sa[NN];     // diagonal of SA

__device__ __forceinline__ float* selbuf(int s) {
    return (s == 0) ? g_S : ((s == 1) ? g_P0 : g_P1);
}

// ---------------- prep: S = skew(Z)/32, P0 = I ----------------
__global__ void prep_kernel(const float* UA, const float* UB, const float* VB,
                            const float* UC, const float* VC) {
    int m = blockIdx.x;
    const float* Z;
    switch (m) { case 0: Z = UA; break; case 1: Z = UB; break; case 2: Z = VB; break;
                 case 3: Z = UC; break; default: Z = VC; break; }
    const float inv = 1.0f / 32.0f;
    for (int idx = blockIdx.y * blockDim.x + threadIdx.x; idx < MM;
         idx += gridDim.y * blockDim.x) {
        int i = idx >> 7, j = idx & 127;
        float v = (i < j) ? Z[idx] : ((i > j) ? -Z[j*NN + i] : 0.0f);
        g_S [m*MM + idx] = v * inv;
        g_P0[m*MM + idx] = (i == j) ? 1.0f : 0.0f;
    }
}

// ---------------- generic 128x128 GEMM stage: O = cI*I + cM*(L@R) ----------
// grid (8 row-tiles of 16, 5 matrices), 256 threads, dynamic smem
__global__ void mm_kernel(int lsel, int rsel, int osel, float cI, float cM) {
    extern __shared__ float sm[];
    float* LsT = sm;            // [k][16] transposed L tile
    float* Rs  = sm + 16*NN;    // [k][j] full R
    const float* L = selbuf(lsel) + blockIdx.y * MM;
    const float* R = selbuf(rsel) + blockIdx.y * MM;
    float*       O = selbuf(osel) + blockIdx.y * MM;
    int r0 = blockIdx.x * 16;
    int tid = threadIdx.x;

    for (int idx = tid; idx < 16*NN; idx += 256) {
        int r = idx >> 7, k = idx & 127;
        LsT[k*16 + r] = L[(r0 + r)*NN + k];
    }
    for (int idx = tid; idx < MM; idx += 256) Rs[idx] = R[idx];
    __syncthreads();

    int rg = tid >> 5;          // 0..7  -> rows 2*rg, 2*rg+1 (within tile)
    int cg = tid & 31;          // 0..31 -> cols 4*cg..4*cg+3
    int r = 2*rg, c = 4*cg;
    float a00=0,a01=0,a02=0,a03=0, a10=0,a11=0,a12=0,a13=0;
    #pragma unroll 4
    for (int k = 0; k < NN; k++) {
        float2 lv = *(const float2*)&LsT[k*16 + r];
        float4 rv = *(const float4*)&Rs[k*NN + c];
        a00 += lv.x*rv.x; a01 += lv.x*rv.y; a02 += lv.x*rv.z; a03 += lv.x*rv.w;
        a10 += lv.y*rv.x; a11 += lv.y*rv.y; a12 += lv.y*rv.z; a13 += lv.y*rv.w;
    }
    float accs[2][4] = {{a00,a01,a02,a03},{a10,a11,a12,a13}};
    #pragma unroll
    for (int a = 0; a < 2; a++)
        #pragma unroll
        for (int b = 0; b < 4; b++) {
            int i = r0 + r + a, j = c + b;
            O[i*NN + j] = cI * ((i == j) ? 1.0f : 0.0f) + cM * accs[a][b];
        }
}

// ---------------- scalars: diagonal of SA ----------------
__global__ void scal_kernel(const float* GA_ks1, const float* GA_k,
                            const float* GA_kp1, const float* SB, const float* SC) {
    if (threadIdx.x != 0) return;
    float b1 = -1.0f, b2 = -1.0f, c1 = -1.0f, c2 = -1.0f;
    for (int i = 0; i < NN; i++) {
        float v = fabsf(SB[i*NN + i]);
        if (v > b1) { b2 = b1; b1 = v; } else if (v > b2) b2 = v;
        float w = fabsf(SC[i*NN + i]);
        if (w > c1) { c2 = c1; c1 = w; } else if (w > c2) c2 = w;
    }
    float sum = b1*b1*c1*c1 + b2*b2*c2*c2;
    float alpha = sqrtf(4.0f * (float)KTOP * sum);   // G = 1
    float sa0 = GA_ks1[0];
    float sa1 = -(alpha + sa0) - (fabsf(GA_k[0]) + EPSV);
    float mn = fminf(fminf(sa0, sa1), 0.0f);         // min over 2x2 block_diag incl. zeros
    g_sa[0] = sa0; g_sa[1] = sa1;
    const int nsk = NN - KTOP;
    for (int i = 0; i < nsk; i++)
        g_sa[2 + i] = mn - fabsf(GA_kp1[i*nsk + i]);
}

// ---------------- build MA/MB/MC: Out = epi( s * L @ diag(d) @ R^T ) -------
// grid (8 row-tiles, 3 modes), 256 threads, dynamic smem
__global__ void build_kernel(int esel, const float* SB, const float* SC, const float* YA) {
    extern __shared__ float sm[];
    float* LsT = sm;             // [k][16] = L[r][k]*d[k]
    float* RsT = sm + 16*NN;     // [k][j]  = R[j][k]
    float* ds  = sm + 16*NN + MM;
    int mode = blockIdx.y;
    const float* E = selbuf(esel);
    const float* L; const float* R;
    if (mode == 0)      { L = E + 0*MM; R = E + 0*MM; }   // A: UA_w, UA_w
    else if (mode == 1) { L = E + 1*MM; R = E + 2*MM; }   // B: UB_w, VB_w
    else                { L = E + 3*MM; R = E + 4*MM; }   // C: UC_w, VC_w
    int r0 = blockIdx.x * 16;
    int tid = threadIdx.x;

    if (tid < NN)
        ds[tid] = (mode == 0) ? g_sa[tid]
                : (mode == 1) ? fabsf(SB[tid*NN + tid]) : fabsf(SC[tid*NN + tid]);
    __syncthreads();
    for (int idx = tid; idx < 16*NN; idx += 256) {
        int r = idx >> 7, k = idx & 127;
        LsT[k*16 + r] = L[(r0 + r)*NN + k] * ds[k];
    }
    for (int idx = tid; idx < MM; idx += 256) {
        int j = idx >> 7, k = idx & 127;
        RsT[k*NN + j] = R[j*NN + k];
    }
    __syncthreads();

    int rg = tid >> 5, cg = tid & 31;
    int r = 2*rg, c = 4*cg;
    float a00=0,a01=0,a02=0,a03=0, a10=0,a11=0,a12=0,a13=0;
    #pragma unroll 4
    for (int k = 0; k < NN; k++) {
        float2 lv = *(const float2*)&LsT[k*16 + r];
        float4 rv = *(const float4*)&RsT[k*NN + c];
        a00 += lv.x*rv.x; a01 += lv.x*rv.y; a02 += lv.x*rv.z; a03 += lv.x*rv.w;
        a10 += lv.y*rv.x; a11 += lv.y*rv.y; a12 += lv.y*rv.z; a13 += lv.y*rv.w;
    }
    float accs[2][4] = {{a00,a01,a02,a03},{a10,a11,a12,a13}};
    #pragma unroll
    for (int a = 0; a < 2; a++)
        #pragma unroll
        for (int b = 0; b < 4; b++) {
            int i = r0 + r + a, j = c + b;
            float acc = accs[a][b];
            if (mode == 0) {   // MA = I + STEP*(0.5*UA SA UA^T + 0.5*skew(YA))
                float sk = (i < j) ? YA[i*NN + j] : ((i > j) ? -YA[j*NN + i] : 0.0f);
                g_MA[i*NN + j] = ((i == j) ? 1.0f : 0.0f)
                               + 0.5f*STEPF*acc + 0.5f*STEPF*sk;
            } else if (mode == 1) {
                g_MB[i*NN + j] = STEPF * acc;    // STEP*B
            } else {
                g_MC[i*NN + j] = acc;            // C
            }
        }
}

// ---------------- recurrence: grid 128 blocks x 4 batch cols, 128 threads --
// smem: A^T,B^T,C^T (3*64KB) + X[128][4] + T[128][4]
__global__ void recur_kernel(const float* __restrict__ X0,
                             const float* __restrict__ bx,
                             const float* __restrict__ by,
                             float* __restrict__ out) {
    extern __shared__ float sm[];
    float* sAT = sm;               // [k][i]
    float* sBT = sm +   MM;
    float* sCT = sm + 2*MM;
    float* sX  = sm + 3*MM;        // [n][c] stride 4
    float* sT  = sX + 512;
    int tid = threadIdx.x;
    int b0  = blockIdx.x * 4;

    for (int idx = tid; idx < MM; idx += 128) {
        int i = idx >> 7, k = idx & 127;
        sAT[k*NN + i] = g_MA[idx];
        sBT[k*NN + i] = g_MB[idx];
        sCT[k*NN + i] = g_MC[idx];
    }
    for (int idx = tid; idx < 512; idx += 128) {
        int n = idx >> 2, c = idx & 3;
        float v = X0[(b0 + c)*NN + n];
        sX[n*4 + c] = v;
        out[(size_t)(b0 + c)*TMAXS*NN + n] = v;    // t = 0
    }
    int rg = tid & 63, cg = tid >> 6;
    int r = 2*rg, c = 2*cg;
    float by0 = by[r], by1 = by[r+1];
    float bx0 = STEPF*bx[r], bx1 = STEPF*bx[r+1];
    __syncthreads();

    for (int t = 1; t < TMAXS; t++) {
        float a00=0,a01=0,a10=0,a11=0, y00=0,y01=0,y10=0,y11=0;
        #pragma unroll 4
        for (int k = 0; k < NN; k++) {
            float2 xk = *(const float2*)&sX [k*4  + c];
            float2 av = *(const float2*)&sAT[k*NN + r];
            float2 cv = *(const float2*)&sCT[k*NN + r];
            a00 += av.x*xk.x; a01 += av.x*xk.y;
            a10 += av.y*xk.x; a11 += av.y*xk.y;
            y00 += cv.x*xk.x; y01 += cv.x*xk.y;
            y10 += cv.y*xk.x; y11 += cv.y*xk.y;
        }
        sT[ r   *4 + c    ] = tanhf(y00 + by0);
        sT[ r   *4 + c + 1] = tanhf(y01 + by0);
        sT[(r+1)*4 + c    ] = tanhf(y10 + by1);
        sT[(r+1)*4 + c + 1] = tanhf(y11 + by1);
        __syncthreads();

        float u00=0,u01=0,u10=0,u11=0;
        #pragma unroll 4
        for (int k = 0; k < NN; k++) {
            float2 tk = *(const float2*)&sT [k*4  + c];
            float2 bv = *(const float2*)&sBT[k*NN + r];
            u00 += bv.x*tk.x; u01 += bv.x*tk.y;
            u10 += bv.y*tk.x; u11 += bv.y*tk.y;
        }
        float x00 = a00 + u00 + bx0;
        float x01 = a01 + u01 + bx0;
        float x10 = a10 + u10 + bx1;
        float x11 = a11 + u11 + bx1;

        sX[ r   *4 + c    ] = x00;
        sX[ r   *4 + c + 1] = x01;
        sX[(r+1)*4 + c    ] = x10;
        sX[(r+1)*4 + c + 1] = x11;

        size_t o0 = ((size_t)(b0 + c    )*TMAXS + t)*NN + r;
        size_t o1 = ((size_t)(b0 + c + 1)*TMAXS + t)*NN + r;
        *(float2*)&out[o0] = make_float2(x00, x10);
        *(float2*)&out[o1] = make_float2(x01, x11);
        __syncthreads();
    }
}

// ---------------- host launcher ----------------
extern "C" void kernel_launch(void* const* d_in, const int* in_sizes, int n_in,
                              void* d_out, int out_size) {
    const float* X0      = (const float*)d_in[0];
    const float* GA_ks1  = (const float*)d_in[1];
    const float* GA_k    = (const float*)d_in[2];
    const float* GA_kp1  = (const float*)d_in[3];
    const float* YA      = (const float*)d_in[4];
    const float* UA      = (const float*)d_in[5];
    const float* UB      = (const float*)d_in[6];
    const float* VB      = (const float*)d_in[7];
    const float* SB      = (const float*)d_in[8];
    const float* UC      = (const float*)d_in[9];
    const float* VC      = (const float*)d_in[10];
    const float* SC      = (const float*)d_in[11];
    const float* bx      = (const float*)d_in[12];
    const float* by      = (const float*)d_in[13];
    float* out = (float*)d_out;

    const int SMEM_MM    = (16*NN + MM) * 4;            // 73728
    const int SMEM_BUILD = (16*NN + MM + NN) * 4;       // 74240
    const int SMEM_RECUR = (3*MM + 512 + 512) * 4;      // 200704

    cudaFuncSetAttribute(mm_kernel,    cudaFuncAttributeMaxDynamicSharedMemorySize, SMEM_MM);
    cudaFuncSetAttribute(build_kernel, cudaFuncAttributeMaxDynamicSharedMemorySize, SMEM_BUILD);
    cudaFuncSetAttribute(recur_kernel, cudaFuncAttributeMaxDynamicSharedMemorySize, SMEM_RECUR);

    // 1) skew + scale, P = I
    prep_kernel<<<dim3(5, 16), 256>>>(UA, UB, VB, UC, VC);

    // 2) Horner Taylor (order 10) of expm(S), S = skew/32
    int cur = 1;
    for (int j = 10; j >= 1; j--) {
        int nxt = (cur == 1) ? 2 : 1;
        mm_kernel<<<dim3(8, 5), 256, SMEM_MM>>>(0, cur, nxt, 1.0f, 1.0f/(float)j);
        cur = nxt;
    }
    // 3) 5 squarings: expm(skew) = (expm(skew/32))^32
    for (int s = 0; s < 5; s++) {
        int nxt = (cur == 1) ? 2 : 1;
        mm_kernel<<<dim3(8, 5), 256, SMEM_MM>>>(cur, cur, nxt, 0.0f, 1.0f);
        cur = nxt;
    }

    // 4) SA diagonal scalars
    scal_kernel<<<1, 32>>>(GA_ks1, GA_k, GA_kp1, SB, SC);

    // 5) build MA = I+STEP*A, MB = STEP*B, MC = C
    build_kernel<<<dim3(8, 3), 256, SMEM_BUILD>>>(cur, SB, SC, YA);

    // 6) sequential recurrence, batch split across 128 independent blocks
    recur_kernel<<<128, 128, SMEM_RECUR>>>(X0, bx, by, out);

    (void)in_sizes; (void)n_in; (void)out_size;
}

// round 3
// speedup vs baseline: 1.2090x; 1.2090x over previous
#include <cuda_runtime.h>
#include <math.h>
#include <stdint.h>

#define NN 128
#define MM (NN*NN)
#define KTOP 2
#define TMAXS 512
#define STEPF 0.01f
#define EPSV 1e-5f
#define BSZ 512

// ---------------- device scratch (static, no allocations) ----------------
__device__ float g_S [5*MM];   // skew(Z)
__device__ float g_S2[5*MM];   // S^2
__device__ float g_S3[5*MM];   // S^3
__device__ float g_P0[5*MM];   // Horner ping
__device__ float g_P1[5*MM];   // Horner pong
__device__ float g_MAT[MM];    // (I + STEP*A)^T   [k][r]
__device__ float g_MBT[MM];    // (STEP*B)^T
__device__ float g_MCT[MM];    // C^T
__device__ float g_sa[NN];     // diagonal of SA

__device__ __forceinline__ float* selbuf(int s) {
    switch (s) { case 0: return g_S; case 1: return g_S2; case 2: return g_S3;
                 case 3: return g_P0; default: return g_P1; }
}

// ---------------- f32x2 helpers ----------------
__device__ __forceinline__ unsigned long long rep2(float v) {
    unsigned long long r;
    asm("mov.b64 %0, {%1, %1};" : "=l"(r) : "f"(v));
    return r;
}
__device__ __forceinline__ void fma2(unsigned long long& a,
                                     unsigned long long b, unsigned long long c) {
    asm("fma.rn.f32x2 %0, %1, %2, %0;" : "+l"(a) : "l"(b), "l"(c));
}
__device__ __forceinline__ void unpk(float& lo, float& hi, unsigned long long v) {
    asm("mov.b64 {%0, %1}, %2;" : "=f"(lo), "=f"(hi) : "l"(v));
}
__device__ __forceinline__ float tanha(float x) {
    float r;
    asm("tanh.approx.f32 %0, %1;" : "=f"(r) : "f"(x));
    return r;
}

// ---------------- prep: S = skew(Z) ----------------
__global__ void prep_kernel(const float* UA, const float* UB, const float* VB,
                            const float* UC, const float* VC) {
    int m = blockIdx.x;
    const float* Z;
    switch (m) { case 0: Z = UA; break; case 1: Z = UB; break; case 2: Z = VB; break;
                 case 3: Z = UC; break; default: Z = VC; break; }
    for (int idx = blockIdx.y * blockDim.x + threadIdx.x; idx < MM;
         idx += gridDim.y * blockDim.x) {
        int i = idx >> 7, j = idx & 127;
        float v = (i < j) ? Z[idx] : ((i > j) ? -Z[j*NN + i] : 0.0f);
        g_S[m*MM + idx] = v;
    }
}

// ---------------- GEMM stage: O = L@R + eI*I + eS*S + eS2*S2 ----------
// dual!=0 (stage computing S2): O = acc, and P0 = dI*I + dS*S + dS2*acc
__global__ __launch_bounds__(256) void mm_kernel(int lsel, int rsel, int osel,
                                                 float eI, float eS, float eS2,
                                                 int dual, float dI, float dS, float dS2) {
    extern __shared__ float sm[];
    float* LsT = sm;            // [k][16] transposed L tile
    float* Rs  = sm + 16*NN;    // [k][j] full R
    int m = blockIdx.y;
    const float* L = selbuf(lsel) + m*MM;
    const float* R = selbuf(rsel) + m*MM;
    float*       O = selbuf(osel) + m*MM;
    const float* Sm  = g_S  + m*MM;
    const float* S2m = g_S2 + m*MM;
    float*       P0m = g_P0 + m*MM;
    int r0 = blockIdx.x * 16;
    int tid = threadIdx.x;

    for (int idx = tid; idx < 16*NN; idx += 256) {
        int r = idx >> 7, k = idx & 127;
        LsT[k*16 + r] = L[(r0 + r)*NN + k];
    }
    for (int idx = tid; idx < MM; idx += 256) Rs[idx] = R[idx];
    __syncthreads();

    int rg = tid >> 5;          // 0..7  -> rows 2*rg, 2*rg+1 (within tile)
    int cg = tid & 31;          // 0..31 -> cols 4*cg..4*cg+3
    int r = 2*rg, c = 4*cg;
    float a00=0,a01=0,a02=0,a03=0, a10=0,a11=0,a12=0,a13=0;
    #pragma unroll 4
    for (int k = 0; k < NN; k++) {
        float2 lv = *(const float2*)&LsT[k*16 + r];
        float4 rv = *(const float4*)&Rs[k*NN + c];
        a00 += lv.x*rv.x; a01 += lv.x*rv.y; a02 += lv.x*rv.z; a03 += lv.x*rv.w;
        a10 += lv.y*rv.x; a11 += lv.y*rv.y; a12 += lv.y*rv.z; a13 += lv.y*rv.w;
    }
    float accs[2][4] = {{a00,a01,a02,a03},{a10,a11,a12,a13}};
    #pragma unroll
    for (int a = 0; a < 2; a++) {
        int i = r0 + r + a;
        int base = i*NN + c;
        float4 accv = make_float4(accs[a][0], accs[a][1], accs[a][2], accs[a][3]);
        float4 sv = *(const float4*)&Sm[base];
        if (dual) {
            *(float4*)&O[base] = accv;
            float4 p;
            p.x = dI*((i == c+0)?1.0f:0.0f) + dS*sv.x + dS2*accv.x;
            p.y = dI*((i == c+1)?1.0f:0.0f) + dS*sv.y + dS2*accv.y;
            p.z = dI*((i == c+2)?1.0f:0.0f) + dS*sv.z + dS2*accv.z;
            p.w = dI*((i == c+3)?1.0f:0.0f) + dS*sv.w + dS2*accv.w;
            *(float4*)&P0m[base] = p;
        } else {
            float4 s2v = *(const float4*)&S2m[base];
            float4 o;
            o.x = accv.x + eI*((i == c+0)?1.0f:0.0f) + eS*sv.x + eS2*s2v.x;
            o.y = accv.y + eI*((i == c+1)?1.0f:0.0f) + eS*sv.y + eS2*s2v.y;
            o.z = accv.z + eI*((i == c+2)?1.0f:0.0f) + eS*sv.z + eS2*s2v.z;
            o.w = accv.w + eI*((i == c+3)?1.0f:0.0f) + eS*sv.w + eS2*s2v.w;
            *(float4*)&O[base] = o;
        }
    }
}

// ---------------- scalars: diagonal of SA ----------------
__global__ void scal_kernel(const float* GA_ks1, const float* GA_k,
                            const float* GA_kp1, const float* SB, const float* SC) {
    if (threadIdx.x != 0) return;
    float b1 = -1.0f, b2 = -1.0f, c1 = -1.0f, c2 = -1.0f;
    for (int i = 0; i < NN; i++) {
        float v = fabsf(SB[i*NN + i]);
        if (v > b1) { b2 = b1; b1 = v; } else if (v > b2) b2 = v;
        float w = fabsf(SC[i*NN + i]);
        if (w > c1) { c2 = c1; c1 = w; } else if (w > c2) c2 = w;
    }
    float sum = b1*b1*c1*c1 + b2*b2*c2*c2;
    float alpha = sqrtf(4.0f * (float)KTOP * sum);   // G = 1
    float sa0 = GA_ks1[0];
    float sa1 = -(alpha + sa0) - (fabsf(GA_k[0]) + EPSV);
    float mn = fminf(fminf(sa0, sa1), 0.0f);         // min over 2x2 block incl. zeros
    g_sa[0] = sa0; g_sa[1] = sa1;
    const int nsk = NN - KTOP;
    for (int i = 0; i < nsk; i++)
        g_sa[2 + i] = mn - fabsf(GA_kp1[i*nsk + i]);
}

// ---------------- build transposed MA/MB/MC in gmem -------
__global__ __launch_bounds__(256) void build_kernel(const float* SB, const float* SC,
                                                    const float* YA) {
    extern __shared__ float sm[];
    float* LsT = sm;             // [k][16] = L[r][k]*d[k]
    float* RsT = sm + 16*NN;     // [k][j]  = R[j][k]
    float* ds  = sm + 16*NN + MM;
    int mode = blockIdx.y;
    const float* L; const float* R;
    if (mode == 0)      { L = g_P0 + 0*MM; R = g_P0 + 0*MM; }   // A: UA_w, UA_w
    else if (mode == 1) { L = g_P0 + 1*MM; R = g_P0 + 2*MM; }   // B: UB_w, VB_w
    else                { L = g_P0 + 3*MM; R = g_P0 + 4*MM; }   // C: UC_w, VC_w
    int r0 = blockIdx.x * 16;
    int tid = threadIdx.x;

    if (tid < NN)
        ds[tid] = (mode == 0) ? g_sa[tid]
                : (mode == 1) ? fabsf(SB[tid*NN + tid]) : fabsf(SC[tid*NN + tid]);
    __syncthreads();
    for (int idx = tid; idx < 16*NN; idx += 256) {
        int r = idx >> 7, k = idx & 127;
        LsT[k*16 + r] = L[(r0 + r)*NN + k] * ds[k];
    }
    for (int idx = tid; idx < MM; idx += 256) {
        int j = idx >> 7, k = idx & 127;
        RsT[k*NN + j] = R[j*NN + k];
    }
    __syncthreads();

    int rg = tid >> 5, cg = tid & 31;
    int r = 2*rg, c = 4*cg;
    float a00=0,a01=0,a02=0,a03=0, a10=0,a11=0,a12=0,a13=0;
    #pragma unroll 4
    for (int k = 0; k < NN; k++) {
        float2 lv = *(const float2*)&LsT[k*16 + r];
        float4 rv = *(const float4*)&RsT[k*NN + c];
        a00 += lv.x*rv.x; a01 += lv.x*rv.y; a02 += lv.x*rv.z; a03 += lv.x*rv.w;
        a10 += lv.y*rv.x; a11 += lv.y*rv.y; a12 += lv.y*rv.z; a13 += lv.y*rv.w;
    }
    float accs[2][4] = {{a00,a01,a02,a03},{a10,a11,a12,a13}};
    #pragma unroll
    for (int a = 0; a < 2; a++)
        #pragma unroll
        for (int b = 0; b < 4; b++) {
            int i = r0 + r + a, j = c + b;
            float acc = accs[a][b];
            if (mode == 0) {   // MA = I + STEP*(0.5*UA SA UA^T + 0.5*skew(YA))
                float sk = (i < j) ? YA[i*NN + j] : ((i > j) ? -YA[j*NN + i] : 0.0f);
                g_MAT[j*NN + i] = ((i == j) ? 1.0f : 0.0f)
                                + 0.5f*STEPF*acc + 0.5f*STEPF*sk;
            } else if (mode == 1) {
                g_MBT[j*NN + i] = STEPF * acc;    // STEP*B
            } else {
                g_MCT[j*NN + i] = acc;            // C
            }
        }
}

// ---------------- recurrence: 128 blocks x 4 batch cols, 128 threads -----
// thread r owns row r for all 4 columns; matrices k-major, X/T broadcast
__global__ __launch_bounds__(128, 1) void recur_kernel(
        const float* __restrict__ X0,
        const float* __restrict__ bx,
        const float* __restrict__ by,
        float* __restrict__ out) {
    extern __shared__ float sm[];
    float* sA = sm;               // [k][r] = MA[r][k]
    float* sB = sm +   MM;
    float* sC = sm + 2*MM;
    float4* sX = (float4*)(sm + 3*MM);   // [128]
    float4* sT = sX + NN;                // [128]
    const int r  = threadIdx.x;
    const int b0 = blockIdx.x << 2;

    {   // conflict-free straight copy (already transposed in gmem)
        const float4* a4 = (const float4*)g_MAT;
        const float4* b4 = (const float4*)g_MBT;
        const float4* c4 = (const float4*)g_MCT;
        float4* da = (float4*)sA; float4* db = (float4*)sB; float4* dc = (float4*)sC;
        #pragma unroll
        for (int i = r; i < MM/4; i += NN) { da[i] = a4[i]; db[i] = b4[i]; dc[i] = c4[i]; }
    }
    float x0 = X0[(b0+0)*NN + r];
    float x1 = X0[(b0+1)*NN + r];
    float x2 = X0[(b0+2)*NN + r];
    float x3 = X0[(b0+3)*NN + r];
    sX[r] = make_float4(x0, x1, x2, x3);

    float* p0 = out + (size_t)(b0+0)*TMAXS*NN + r;
    float* p1 = out + (size_t)(b0+1)*TMAXS*NN + r;
    float* p2 = out + (size_t)(b0+2)*TMAXS*NN + r;
    float* p3 = out + (size_t)(b0+3)*TMAXS*NN + r;
    *p0 = x0; *p1 = x1; *p2 = x2; *p3 = x3;
    p0 += NN; p1 += NN; p2 += NN; p3 += NN;

    const unsigned long long bx2 = rep2(STEPF * bx[r]);
    const unsigned long long by2 = rep2(by[r]);
    __syncthreads();

    for (int t = 1; t < TMAXS; t++) {
        unsigned long long a01 = bx2, a23 = bx2, y01 = by2, y23 = by2;
        #pragma unroll 4
        for (int k = 0; k < NN; k++) {
            ulonglong2 xp = *(const ulonglong2*)(sX + k);   // broadcast 16B
            unsigned long long av = rep2(sA[k*NN + r]);
            unsigned long long cv = rep2(sC[k*NN + r]);
            fma2(a01, av, xp.x); fma2(a23, av, xp.y);
            fma2(y01, cv, xp.x); fma2(y23, cv, xp.y);
        }
        float y0, y1, y2, y3;
        unpk(y0, y1, y01); unpk(y2, y3, y23);
        sT[r] = make_float4(tanha(y0), tanha(y1), tanha(y2), tanha(y3));
        __syncthreads();

        #pragma unroll 4
        for (int k = 0; k < NN; k++) {
            ulonglong2 tp = *(const ulonglong2*)(sT + k);   // broadcast 16B
            unsigned long long bv = rep2(sB[k*NN + r]);
            fma2(a01, bv, tp.x); fma2(a23, bv, tp.y);
        }
        float n0, n1, n2, n3;
        unpk(n0, n1, a01); unpk(n2, n3, a23);
        sX[r] = make_float4(n0, n1, n2, n3);
        *p0 = n0; *p1 = n1; *p2 = n2; *p3 = n3;
        p0 += NN; p1 += NN; p2 += NN; p3 += NN;
        __syncthreads();
    }
}

// ---------------- host launcher ----------------
extern "C" void kernel_launch(void* const* d_in, const int* in_sizes, int n_in,
                              void* d_out, int out_size) {
    const float* X0      = (const float*)d_in[0];
    const float* GA_ks1  = (const float*)d_in[1];
    const float* GA_k    = (const float*)d_in[2];
    const float* GA_kp1  = (const float*)d_in[3];
    const float* YA      = (const float*)d_in[4];
    const float* UA      = (const float*)d_in[5];
    const float* UB      = (const float*)d_in[6];
    const float* VB      = (const float*)d_in[7];
    const float* SB      = (const float*)d_in[8];
    const float* UC      = (const float*)d_in[9];
    const float* VC      = (const float*)d_in[10];
    const float* SC      = (const float*)d_in[11];
    const float* bx      = (const float*)d_in[12];
    const float* by      = (const float*)d_in[13];
    float* out = (float*)d_out;

    const int SMEM_MM    = (16*NN + MM) * 4;            // 73728
    const int SMEM_BUILD = (16*NN + MM + NN) * 4;       // 74240
    const int SMEM_RECUR = (3*MM + 2*4*NN) * 4;         // 200704

    cudaFuncSetAttribute(mm_kernel,    cudaFuncAttributeMaxDynamicSharedMemorySize, SMEM_MM);
    cudaFuncSetAttribute(build_kernel, cudaFuncAttributeMaxDynamicSharedMemorySize, SMEM_BUILD);
    cudaFuncSetAttribute(recur_kernel, cudaFuncAttributeMaxDynamicSharedMemorySize, SMEM_RECUR);

    // Taylor coefficients 1/m!
    const float c3 = 1.6666667e-1f, c4 = 4.1666667e-2f, c5 = 8.3333333e-3f;
    const float c6 = 1.3888889e-3f, c7 = 1.9841270e-4f, c8 = 2.4801587e-5f;
    const float c9 = 2.7557319e-6f, c10 = 2.7557319e-7f, c11 = 2.5052108e-8f;
    const float c12 = 2.0876757e-9f, c13 = 1.6059044e-10f, c14 = 1.1470746e-11f;

    // 1) S = skew(Z)
    prep_kernel<<<dim3(5, 16), 256>>>(UA, UB, VB, UC, VC);

    // 2) expm via degree-14 Taylor, Paterson-Stockmeyer (Z = S^3):
    //    S2 = S*S, also P0 = B4 = c12 I + c13 S + c14 S2
    mm_kernel<<<dim3(8, 5), 256, SMEM_MM>>>(0, 0, 1, 0,0,0, 1, c12, c13, c14);
    //    S3 = S2*S
    mm_kernel<<<dim3(8, 5), 256, SMEM_MM>>>(1, 0, 2, 0,0,0, 0, 0,0,0);
    //    P1 = P0*Z + B3
    mm_kernel<<<dim3(8, 5), 256, SMEM_MM>>>(3, 2, 4, c9, c10, c11, 0, 0,0,0);
    //    P0 = P1*Z + B2
    mm_kernel<<<dim3(8, 5), 256, SMEM_MM>>>(4, 2, 3, c6, c7, c8, 0, 0,0,0);
    //    P1 = P0*Z + B1
    mm_kernel<<<dim3(8, 5), 256, SMEM_MM>>>(3, 2, 4, c3, c4, c5, 0, 0,0,0);
    //    P0 = P1*Z + B0   (final expm in g_P0)
    mm_kernel<<<dim3(8, 5), 256, SMEM_MM>>>(4, 2, 3, 1.0f, 1.0f, 0.5f, 0, 0,0,0);

    // 3) SA diagonal scalars
    scal_kernel<<<1, 32>>>(GA_ks1, GA_k, GA_kp1, SB, SC);

    // 4) build transposed MA/MB/MC
    build_kernel<<<dim3(8, 3), 256, SMEM_BUILD>>>(SB, SC, YA);

    // 5) sequential recurrence, batch split across 128 independent blocks
    recur_kernel<<<128, NN, SMEM_RECUR>>>(X0, bx, by, out);

    (void)in_sizes; (void)n_in; (void)out_size;
}

// round 4
// speedup vs baseline: 1.6762x; 1.3865x over previous
#include <cuda_runtime.h>
#include <math.h>
#include <stdint.h>

#define NN 128
#define MM (NN*NN)
#define KTOP 2
#define TMAXS 512
#define STEPF 0.01f
#define EPSV 1e-5f
#define BSZ 512

// ---------------- device scratch (static, no allocations) ----------------
__device__ float g_S [5*MM];   // skew(Z)
__device__ float g_S2[5*MM];   // S^2
__device__ float g_S3[5*MM];   // S^3
__device__ float g_P0[5*MM];   // Horner ping
__device__ float g_P1[5*MM];   // Horner pong (final expm lands here)
__device__ float g_MAT[MM];    // (I + STEP*A)^T   [k][r]
__device__ float g_MBT[MM];    // (STEP*B)^T
__device__ float g_MCT[MM];    // C^T
__device__ float g_sa[NN];     // diagonal of SA

__device__ __forceinline__ float* selbuf(int s) {
    switch (s) { case 0: return g_S; case 1: return g_S2; case 2: return g_S3;
                 case 3: return g_P0; default: return g_P1; }
}

// ---------------- f32x2 helpers ----------------
typedef unsigned long long ull;
__device__ __forceinline__ ull rep2(float v) {
    ull r; asm("mov.b64 %0, {%1, %1};" : "=l"(r) : "f"(v)); return r;
}
__device__ __forceinline__ ull pk2(float lo, float hi) {
    ull r; asm("mov.b64 %0, {%1, %2};" : "=l"(r) : "f"(lo), "f"(hi)); return r;
}
__device__ __forceinline__ void fma2(ull& a, ull b, ull c) {
    asm("fma.rn.f32x2 %0, %1, %2, %0;" : "+l"(a) : "l"(b), "l"(c));
}
__device__ __forceinline__ void add2(ull& a, ull b) {
    asm("add.rn.f32x2 %0, %0, %1;" : "+l"(a) : "l"(b));
}
__device__ __forceinline__ void unpk(float& lo, float& hi, ull v) {
    asm("mov.b64 {%0, %1}, %2;" : "=f"(lo), "=f"(hi) : "l"(v));
}
__device__ __forceinline__ float tanha(float x) {
    float r; asm("tanh.approx.f32 %0, %1;" : "=f"(r) : "f"(x)); return r;
}
__device__ __forceinline__ ull red4(ull v) {   // sum across 4 q-lanes (lane bits 0..1)
    ull o = __shfl_xor_sync(0xffffffffu, v, 1); add2(v, o);
    o     = __shfl_xor_sync(0xffffffffu, v, 2); add2(v, o);
    return v;
}

// ---------------- prep: S = skew(Z) ----------------
__global__ void prep_kernel(const float* UA, const float* UB, const float* VB,
                            const float* UC, const float* VC) {
    int m = blockIdx.x;
    const float* Z;
    switch (m) { case 0: Z = UA; break; case 1: Z = UB; break; case 2: Z = VB; break;
                 case 3: Z = UC; break; default: Z = VC; break; }
    for (int idx = blockIdx.y * blockDim.x + threadIdx.x; idx < MM;
         idx += gridDim.y * blockDim.x) {
        int i = idx >> 7, j = idx & 127;
        float v = (i < j) ? Z[idx] : ((i > j) ? -Z[j*NN + i] : 0.0f);
        g_S[m*MM + idx] = v;
    }
}

// ---------------- GEMM stage: O = L@R + eI*I + eS*S + eS2*S2 ----------
// dual!=0 (stage computing S2): O = acc, and P0 = dI*I + dS*S + dS2*acc
__global__ __launch_bounds__(256) void mm_kernel(int lsel, int rsel, int osel,
                                                 float eI, float eS, float eS2,
                                                 int dual, float dI, float dS, float dS2) {
    extern __shared__ float sm[];
    float* LsT = sm;            // [k][16] transposed L tile
    float* Rs  = sm + 16*NN;    // [k][j] full R
    int m = blockIdx.y;
    const float* L = selbuf(lsel) + m*MM;
    const float* R = selbuf(rsel) + m*MM;
    float*       O = selbuf(osel) + m*MM;
    const float* Sm  = g_S  + m*MM;
    const float* S2m = g_S2 + m*MM;
    float*       P0m = g_P0 + m*MM;
    int r0 = blockIdx.x * 16;
    int tid = threadIdx.x;

    for (int idx = tid; idx < 16*NN; idx += 256) {
        int r = idx >> 7, k = idx & 127;
        LsT[k*16 + r] = L[(r0 + r)*NN + k];
    }
    for (int idx = tid; idx < MM; idx += 256) Rs[idx] = R[idx];
    __syncthreads();

    int rg = tid >> 5, cg = tid & 31;
    int r = 2*rg, c = 4*cg;
    float a00=0,a01=0,a02=0,a03=0, a10=0,a11=0,a12=0,a13=0;
    #pragma unroll 4
    for (int k = 0; k < NN; k++) {
        float2 lv = *(const float2*)&LsT[k*16 + r];
        float4 rv = *(const float4*)&Rs[k*NN + c];
        a00 += lv.x*rv.x; a01 += lv.x*rv.y; a02 += lv.x*rv.z; a03 += lv.x*rv.w;
        a10 += lv.y*rv.x; a11 += lv.y*rv.y; a12 += lv.y*rv.z; a13 += lv.y*rv.w;
    }
    float accs[2][4] = {{a00,a01,a02,a03},{a10,a11,a12,a13}};
    #pragma unroll
    for (int a = 0; a < 2; a++) {
        int i = r0 + r + a;
        int base = i*NN + c;
        float4 accv = make_float4(accs[a][0], accs[a][1], accs[a][2], accs[a][3]);
        float4 sv = *(const float4*)&Sm[base];
        if (dual) {
            *(float4*)&O[base] = accv;
            float4 p;
            p.x = dI*((i == c+0)?1.0f:0.0f) + dS*sv.x + dS2*accv.x;
            p.y = dI*((i == c+1)?1.0f:0.0f) + dS*sv.y + dS2*accv.y;
            p.z = dI*((i == c+2)?1.0f:0.0f) + dS*sv.z + dS2*accv.z;
            p.w = dI*((i == c+3)?1.0f:0.0f) + dS*sv.w + dS2*accv.w;
            *(float4*)&P0m[base] = p;
        } else {
            float4 s2v = *(const float4*)&S2m[base];
            float4 o;
            o.x = accv.x + eI*((i == c+0)?1.0f:0.0f) + eS*sv.x + eS2*s2v.x;
            o.y = accv.y + eI*((i == c+1)?1.0f:0.0f) + eS*sv.y + eS2*s2v.y;
            o.z = accv.z + eI*((i == c+2)?1.0f:0.0f) + eS*sv.z + eS2*s2v.z;
            o.w = accv.w + eI*((i == c+3)?1.0f:0.0f) + eS*sv.w + eS2*s2v.w;
            *(float4*)&O[base] = o;
        }
    }
}

// ---------------- scalars: diagonal of SA ----------------
__global__ void scal_kernel(const float* GA_ks1, const float* GA_k,
                            const float* GA_kp1, const float* SB, const float* SC) {
    if (threadIdx.x != 0) return;
    float b1 = -1.0f, b2 = -1.0f, c1 = -1.0f, c2 = -1.0f;
    for (int i = 0; i < NN; i++) {
        float v = fabsf(SB[i*NN + i]);
        if (v > b1) { b2 = b1; b1 = v; } else if (v > b2) b2 = v;
        float w = fabsf(SC[i*NN + i]);
        if (w > c1) { c2 = c1; c1 = w; } else if (w > c2) c2 = w;
    }
    float sum = b1*b1*c1*c1 + b2*b2*c2*c2;
    float alpha = sqrtf(4.0f * (float)KTOP * sum);   // G = 1
    float sa0 = GA_ks1[0];
    float sa1 = -(alpha + sa0) - (fabsf(GA_k[0]) + EPSV);
    float mn = fminf(fminf(sa0, sa1), 0.0f);
    g_sa[0] = sa0; g_sa[1] = sa1;
    const int nsk = NN - KTOP;
    for (int i = 0; i < nsk; i++)
        g_sa[2 + i] = mn - fabsf(GA_kp1[i*nsk + i]);
}

// ---------------- build transposed MA/MB/MC in gmem (expm in g_P1) -------
__global__ __launch_bounds__(256) void build_kernel(const float* SB, const float* SC,
                                                    const float* YA) {
    extern __shared__ float sm[];
    float* LsT = sm;             // [k][16] = L[r][k]*d[k]
    float* RsT = sm + 16*NN;     // [k][j]  = R[j][k]
    float* ds  = sm + 16*NN + MM;
    int mode = blockIdx.y;
    const float* L; const float* R;
    if (mode == 0)      { L = g_P1 + 0*MM; R = g_P1 + 0*MM; }   // A: UA_w, UA_w
    else if (mode == 1) { L = g_P1 + 1*MM; R = g_P1 + 2*MM; }   // B: UB_w, VB_w
    else                { L = g_P1 + 3*MM; R = g_P1 + 4*MM; }   // C: UC_w, VC_w
    int r0 = blockIdx.x * 16;
    int tid = threadIdx.x;

    if (tid < NN)
        ds[tid] = (mode == 0) ? g_sa[tid]
                : (mode == 1) ? fabsf(SB[tid*NN + tid]) : fabsf(SC[tid*NN + tid]);
    __syncthreads();
    for (int idx = tid; idx < 16*NN; idx += 256) {
        int r = idx >> 7, k = idx & 127;
        LsT[k*16 + r] = L[(r0 + r)*NN + k] * ds[k];
    }
    for (int idx = tid; idx < MM; idx += 256) {
        int j = idx >> 7, k = idx & 127;
        RsT[k*NN + j] = R[j*NN + k];
    }
    __syncthreads();

    int rg = tid >> 5, cg = tid & 31;
    int r = 2*rg, c = 4*cg;
    float a00=0,a01=0,a02=0,a03=0, a10=0,a11=0,a12=0,a13=0;
    #pragma unroll 4
    for (int k = 0; k < NN; k++) {
        float2 lv = *(const float2*)&LsT[k*16 + r];
        float4 rv = *(const float4*)&RsT[k*NN + c];
        a00 += lv.x*rv.x; a01 += lv.x*rv.y; a02 += lv.x*rv.z; a03 += lv.x*rv.w;
        a10 += lv.y*rv.x; a11 += lv.y*rv.y; a12 += lv.y*rv.z; a13 += lv.y*rv.w;
    }
    float accs[2][4] = {{a00,a01,a02,a03},{a10,a11,a12,a13}};
    #pragma unroll
    for (int a = 0; a < 2; a++)
        #pragma unroll
        for (int b = 0; b < 4; b++) {
            int i = r0 + r + a, j = c + b;
            float acc = accs[a][b];
            if (mode == 0) {   // MA = I + STEP*(0.5*UA SA UA^T + 0.5*skew(YA))
                float sk = (i < j) ? YA[i*NN + j] : ((i > j) ? -YA[j*NN + i] : 0.0f);
                g_MAT[j*NN + i] = ((i == j) ? 1.0f : 0.0f)
                                + 0.5f*STEPF*acc + 0.5f*STEPF*sk;
            } else if (mode == 1) {
                g_MBT[j*NN + i] = STEPF * acc;    // STEP*B
            } else {
                g_MCT[j*NN + i] = acc;            // C
            }
        }
}

// ---------------- recurrence: 128 blocks, 512 threads, 4 cols/block ------
// thread (r,q): row r = tid>>2, k-phase q = tid&3 handles k = 4*kk+q.
// Matrices live in registers (96 floats/thread); X/T broadcast via SMEM.
__global__ __launch_bounds__(512, 1) void recur_kernel(
        const float* __restrict__ X0,
        const float* __restrict__ bx,
        const float* __restrict__ by,
        float* __restrict__ out) {
    __shared__ float4 sX[NN];
    __shared__ float4 sT[NN];
    const int tid = threadIdx.x;
    const int r = tid >> 2;
    const int q = tid & 3;
    const int b0 = blockIdx.x << 2;

    // register-resident matrix slices
    float rA[32], rB[32], rC[32];
    #pragma unroll
    for (int kk = 0; kk < 32; kk++) {
        int k = 4*kk + q;
        rA[kk] = g_MAT[k*NN + r];
        rB[kk] = g_MBT[k*NN + r];
        rC[kk] = g_MCT[k*NN + r];
    }

    // init X and t=0 output (col q, row r)
    float v = X0[(b0 + q)*NN + r];
    ((float*)sX)[r*4 + q] = v;
    float* p = out + ((size_t)(b0 + q)*TMAXS)*NN + r;
    *p = v; p += NN;

    const ull bx2 = rep2(STEPF * bx[r]);
    const ull by2 = rep2(by[r]);
    __syncthreads();

    for (int t = 1; t < TMAXS; t++) {
        ull a01 = 0, a23 = 0, y01 = 0, y23 = 0;
        #pragma unroll
        for (int kk = 0; kk < 32; kk++) {
            float4 xp = sX[4*kk + q];
            ull x01 = pk2(xp.x, xp.y), x23 = pk2(xp.z, xp.w);
            ull av = rep2(rA[kk]);
            ull cv = rep2(rC[kk]);
            fma2(a01, av, x01); fma2(a23, av, x23);
            fma2(y01, cv, x01); fma2(y23, cv, x23);
        }
        y01 = red4(y01); y23 = red4(y23);
        add2(y01, by2);  add2(y23, by2);
        float y0, y1, y2, y3;
        unpk(y0, y1, y01); unpk(y2, y3, y23);
        float ysel = (q & 2) ? ((q & 1) ? y3 : y2) : ((q & 1) ? y1 : y0);
        ((float*)sT)[r*4 + q] = tanha(ysel);
        __syncthreads();

        #pragma unroll
        for (int kk = 0; kk < 32; kk++) {
            float4 tp = sT[4*kk + q];
            ull t01 = pk2(tp.x, tp.y), t23 = pk2(tp.z, tp.w);
            ull bv = rep2(rB[kk]);
            fma2(a01, bv, t01); fma2(a23, bv, t23);
        }
        a01 = red4(a01); a23 = red4(a23);
        add2(a01, bx2);  add2(a23, bx2);
        float n0, n1, n2, n3;
        unpk(n0, n1, a01); unpk(n2, n3, a23);
        float nsel = (q & 2) ? ((q & 1) ? n3 : n2) : ((q & 1) ? n1 : n0);
        ((float*)sX)[r*4 + q] = nsel;
        *p = nsel; p += NN;
        __syncthreads();
    }
}

// ---------------- host launcher ----------------
extern "C" void kernel_launch(void* const* d_in, const int* in_sizes, int n_in,
                              void* d_out, int out_size) {
    const float* X0      = (const float*)d_in[0];
    const float* GA_ks1  = (const float*)d_in[1];
    const float* GA_k    = (const float*)d_in[2];
    const float* GA_kp1  = (const float*)d_in[3];
    const float* YA      = (const float*)d_in[4];
    const float* UA      = (const float*)d_in[5];
    const float* UB      = (const float*)d_in[6];
    const float* VB      = (const float*)d_in[7];
    const float* SB      = (const float*)d_in[8];
    const float* UC      = (const float*)d_in[9];
    const float* VC      = (const float*)d_in[10];
    const float* SC      = (const float*)d_in[11];
    const float* bx      = (const float*)d_in[12];
    const float* by      = (const float*)d_in[13];
    float* out = (float*)d_out;

    const int SMEM_MM    = (16*NN + MM) * 4;            // 73728
    const int SMEM_BUILD = (16*NN + MM + NN) * 4;       // 74240

    cudaFuncSetAttribute(mm_kernel,    cudaFuncAttributeMaxDynamicSharedMemorySize, SMEM_MM);
    cudaFuncSetAttribute(build_kernel, cudaFuncAttributeMaxDynamicSharedMemorySize, SMEM_BUILD);

    // Taylor 1/m!
    const float c3 = 1.6666667e-1f, c4 = 4.1666667e-2f, c5 = 8.3333333e-3f;
    const float c6 = 1.3888889e-3f, c7 = 1.9841270e-4f, c8 = 2.4801587e-5f;
    const float c9 = 2.7557319e-6f, c10 = 2.7557319e-7f;

    // 1) S = skew(Z)
    prep_kernel<<<dim3(5, 16), 256>>>(UA, UB, VB, UC, VC);

    // 2) expm via degree-10 Taylor, Paterson-Stockmeyer (Z = S^3):
    //    S2 = S*S;  P0 = B3 = c9 I + c10 S
    mm_kernel<<<dim3(8, 5), 256, SMEM_MM>>>(0, 0, 1, 0,0,0, 1, c9, c10, 0.0f);
    //    S3 = S2*S
    mm_kernel<<<dim3(8, 5), 256, SMEM_MM>>>(1, 0, 2, 0,0,0, 0, 0,0,0);
    //    P1 = P0*Z + B2
    mm_kernel<<<dim3(8, 5), 256, SMEM_MM>>>(3, 2, 4, c6, c7, c8, 0, 0,0,0);
    //    P0 = P1*Z + B1
    mm_kernel<<<dim3(8, 5), 256, SMEM_MM>>>(4, 2, 3, c3, c4, c5, 0, 0,0,0);
    //    P1 = P0*Z + B0   (final expm in g_P1)
    mm_kernel<<<dim3(8, 5), 256, SMEM_MM>>>(3, 2, 4, 1.0f, 1.0f, 0.5f, 0, 0,0,0);

    // 3) SA diagonal scalars
    scal_kernel<<<1, 32>>>(GA_ks1, GA_k, GA_kp1, SB, SC);

    // 4) build transposed MA/MB/MC
    build_kernel<<<dim3(8, 3), 256, SMEM_BUILD>>>(SB, SC, YA);

    // 5) sequential recurrence, batch split across 128 independent blocks
    recur_kernel<<<128, 512>>>(X0, bx, by, out);

    (void)in_sizes; (void)n_in; (void)out_size;
}